// round 1
// baseline (speedup 1.0000x reference)
#include <cuda_runtime.h>
#include <math.h>

// Scratch accumulator (no device allocation allowed -> __device__ global).
__device__ double g_loss_sum;

__global__ void zero_kernel() {
    g_loss_sum = 0.0;
}

// y1 viewed as float4: nvec = N*D/4 elements. D=16 -> 4 float4 segments per row.
// Lane groups of 4 (lanes 4k..4k+3) each own one row per iteration.
__global__ void __launch_bounds__(256, 8)
reduce_kernel(const float4* __restrict__ y, long long nvec) {
    long long tid    = (long long)blockIdx.x * blockDim.x + threadIdx.x;
    long long stride = (long long)gridDim.x * blockDim.x;   // multiple of 4

    float acc = 0.0f;
    for (long long v = tid; v < nvec; v += stride) {
        float4 f = y[v];
        float s = f.x * f.x + f.y * f.y + f.z * f.z + f.w * f.w;
        // combine the 4 segments of this row (lanes v%4 == 0..3 of same row)
        s += __shfl_xor_sync(0xFFFFFFFFu, s, 1);
        s += __shfl_xor_sync(0xFFFFFFFFu, s, 2);
        float r = sqrtf(s) - 1.0f;
        // all 4 lanes hold identical r; scale by 1/4 so the group sums to (r)^2
        acc += 0.25f * r * r;
    }

    // warp reduce
    #pragma unroll
    for (int m = 16; m > 0; m >>= 1)
        acc += __shfl_xor_sync(0xFFFFFFFFu, acc, m);

    __shared__ float warp_sums[8];
    int wid = threadIdx.x >> 5;
    int lid = threadIdx.x & 31;
    if (lid == 0) warp_sums[wid] = acc;
    __syncthreads();

    if (wid == 0) {
        float b = (lid < (blockDim.x >> 5)) ? warp_sums[lid] : 0.0f;
        #pragma unroll
        for (int m = 4; m > 0; m >>= 1)
            b += __shfl_xor_sync(0xFFFFFFFFu, b, m);
        if (lid == 0)
            atomicAdd(&g_loss_sum, (double)b);
    }
}

__global__ void finalize_kernel(float* __restrict__ out, double inv_scale) {
    out[0] = (float)(g_loss_sum * inv_scale);
}

extern "C" void kernel_launch(void* const* d_in, const int* in_sizes, int n_in,
                              void* d_out, int out_size) {
    const float4* y = (const float4*)d_in[0];
    long long n_elems = (long long)in_sizes[0];   // N * D
    long long nvec = n_elems / 4;

    // LAMBDA1 = 1.0 ; mean over all N*D elements
    double inv_scale = 1.0 / (double)n_elems;

    zero_kernel<<<1, 1>>>();
    reduce_kernel<<<8192, 256>>>(y, nvec);
    finalize_kernel<<<1, 1>>>((float*)d_out, inv_scale);
}

// round 2
// speedup vs baseline: 1.0712x; 1.0712x over previous
#include <cuda_runtime.h>
#include <math.h>

#define NBLOCKS 4096
#define NTHREADS 256

// Scratch (no device allocation allowed -> __device__ globals).
__device__ float        g_partials[NBLOCKS];
__device__ unsigned int g_ticket = 0;   // reset to 0 by last block each run

__device__ __forceinline__ float row_sq(const float4* __restrict__ y4, long long r) {
    // one full row = 4 contiguous float4 (64 bytes)
    float4 a = __ldcs(&y4[r * 4 + 0]);
    float4 b = __ldcs(&y4[r * 4 + 1]);
    float4 c = __ldcs(&y4[r * 4 + 2]);
    float4 d = __ldcs(&y4[r * 4 + 3]);
    float s = a.x * a.x + a.y * a.y + a.z * a.z + a.w * a.w;
    s      += b.x * b.x + b.y * b.y + b.z * b.z + b.w * b.w;
    s      += c.x * c.x + c.y * c.y + c.z * c.z + c.w * c.w;
    s      += d.x * d.x + d.y * d.y + d.z * d.z + d.w * d.w;
    return s;
}

__global__ void __launch_bounds__(NTHREADS, 8)
loss_kernel(const float4* __restrict__ y4, long long rows,
            float* __restrict__ out, float inv_scale) {
    const long long tid = (long long)blockIdx.x * NTHREADS + threadIdx.x;
    const long long T   = (long long)gridDim.x * NTHREADS;

    float acc = 0.0f;
    long long r = tid;
    // 4-row unrolled mainloop: 16 independent LDG.128 in flight per thread
    for (; r + 3 * T < rows; r += 4 * T) {
        float s0 = row_sq(y4, r);
        float s1 = row_sq(y4, r + T);
        float s2 = row_sq(y4, r + 2 * T);
        float s3 = row_sq(y4, r + 3 * T);
        float d0 = sqrtf(s0) - 1.0f;
        float d1 = sqrtf(s1) - 1.0f;
        float d2 = sqrtf(s2) - 1.0f;
        float d3 = sqrtf(s3) - 1.0f;
        acc += d0 * d0 + d1 * d1 + d2 * d2 + d3 * d3;
    }
    for (; r < rows; r += T) {
        float d = sqrtf(row_sq(y4, r)) - 1.0f;
        acc += d * d;
    }

    // block reduction
    #pragma unroll
    for (int m = 16; m > 0; m >>= 1)
        acc += __shfl_xor_sync(0xFFFFFFFFu, acc, m);

    __shared__ float warp_sums[NTHREADS / 32];
    int wid = threadIdx.x >> 5;
    int lid = threadIdx.x & 31;
    if (lid == 0) warp_sums[wid] = acc;
    __syncthreads();

    if (wid == 0) {
        float b = (lid < NTHREADS / 32) ? warp_sums[lid] : 0.0f;
        #pragma unroll
        for (int m = 4; m > 0; m >>= 1)
            b += __shfl_xor_sync(0xFFFFFFFFu, b, m);
        if (lid == 0)
            g_partials[blockIdx.x] = b;
    }

    // last-block fan-in
    __shared__ bool is_last;
    __threadfence();
    if (threadIdx.x == 0) {
        unsigned int old = atomicAdd(&g_ticket, 1u);
        is_last = (old == gridDim.x - 1u);
    }
    __syncthreads();

    if (is_last) {
        float s = 0.0f;
        for (int i = threadIdx.x; i < (int)gridDim.x; i += NTHREADS)
            s += g_partials[i];
        #pragma unroll
        for (int m = 16; m > 0; m >>= 1)
            s += __shfl_xor_sync(0xFFFFFFFFu, s, m);
        if (lid == 0) warp_sums[wid] = s;
        __syncthreads();
        if (wid == 0) {
            float b = (lid < NTHREADS / 32) ? warp_sums[lid] : 0.0f;
            #pragma unroll
            for (int m = 4; m > 0; m >>= 1)
                b += __shfl_xor_sync(0xFFFFFFFFu, b, m);
            if (lid == 0) {
                out[0]   = b * inv_scale;   // LAMBDA1 = 1.0
                g_ticket = 0;               // reset for next graph replay
            }
        }
    }
}

extern "C" void kernel_launch(void* const* d_in, const int* in_sizes, int n_in,
                              void* d_out, int out_size) {
    const float4* y4 = (const float4*)d_in[0];
    long long n_elems = (long long)in_sizes[0];   // N * D
    long long rows    = n_elems / 16;             // D = 16
    float inv_scale   = (float)(1.0 / (double)n_elems);

    loss_kernel<<<NBLOCKS, NTHREADS>>>(y4, rows, (float*)d_out, inv_scale);
}

// round 3
// speedup vs baseline: 1.1619x; 1.0846x over previous
#include <cuda_runtime.h>
#include <math.h>

#define NBLOCKS  1184            // 148 SMs * 8 blocks — one perfectly balanced wave
#define NTHREADS 256
#define UNROLL   4

__device__ float        g_partials[NBLOCKS];
__device__ unsigned int g_ticket = 0;

// Combine a per-float4 sum-of-squares into the full row sum (lane quads own a
// row: lanes 4j..4j+3 hold the 4 segments), then return this quad's loss
// contribution share (0.25 * (|row|-1)^2 in every lane of the quad).
__device__ __forceinline__ float quad_loss(float s, unsigned mask, bool active) {
    s += __shfl_xor_sync(mask, s, 1);
    s += __shfl_xor_sync(mask, s, 2);
    float r = sqrtf(s) - 1.0f;
    return active ? 0.25f * r * r : 0.0f;
}

__global__ void __launch_bounds__(NTHREADS)
loss_kernel(const float4* __restrict__ y4, long long nvec,
            float* __restrict__ out, float inv_scale) {
    const long long tid = (long long)blockIdx.x * NTHREADS + threadIdx.x;
    const long long T   = (long long)NBLOCKS * NTHREADS;   // multiple of 4

    // Uniform main-loop trip count (identical for every thread -> no divergence)
    const long long kfull = nvec / (UNROLL * T);

    float acc = 0.0f;
    for (long long k = 0; k < kfull; k++) {
        long long v = tid + k * (UNROLL * T);
        // front-batched independent coalesced loads
        float4 a = __ldcs(&y4[v]);
        float4 b = __ldcs(&y4[v + T]);
        float4 c = __ldcs(&y4[v + 2 * T]);
        float4 d = __ldcs(&y4[v + 3 * T]);
        float s0 = a.x * a.x + a.y * a.y + a.z * a.z + a.w * a.w;
        float s1 = b.x * b.x + b.y * b.y + b.z * b.z + b.w * b.w;
        float s2 = c.x * c.x + c.y * c.y + c.z * c.z + c.w * c.w;
        float s3 = d.x * d.x + d.y * d.y + d.z * d.z + d.w * d.w;
        acc += quad_loss(s0, 0xFFFFFFFFu, true);
        acc += quad_loss(s1, 0xFFFFFFFFu, true);
        acc += quad_loss(s2, 0xFFFFFFFFu, true);
        acc += quad_loss(s3, 0xFFFFFFFFu, true);
    }

    // Predicated uniform tail (nvec % 4 == 0 -> quad-uniform activity)
    {
        long long base = kfull * (UNROLL * T);
        #pragma unroll
        for (int t = 0; t < UNROLL; t++) {
            long long v = base + (long long)t * T + tid;
            bool active = v < nvec;
            float s = 0.0f;
            if (active) {
                float4 a = __ldcs(&y4[v]);
                s = a.x * a.x + a.y * a.y + a.z * a.z + a.w * a.w;
            }
            acc += quad_loss(s, 0xFFFFFFFFu, active);
        }
    }

    // block reduction
    #pragma unroll
    for (int m = 16; m > 0; m >>= 1)
        acc += __shfl_xor_sync(0xFFFFFFFFu, acc, m);

    __shared__ float warp_sums[NTHREADS / 32];
    int wid = threadIdx.x >> 5;
    int lid = threadIdx.x & 31;
    if (lid == 0) warp_sums[wid] = acc;
    __syncthreads();

    if (wid == 0) {
        float b = (lid < NTHREADS / 32) ? warp_sums[lid] : 0.0f;
        #pragma unroll
        for (int m = 4; m > 0; m >>= 1)
            b += __shfl_xor_sync(0xFFFFFFFFu, b, m);
        if (lid == 0)
            g_partials[blockIdx.x] = b;
    }

    // single-kernel fan-in: last block reduces the partials
    __shared__ bool is_last;
    __threadfence();
    if (threadIdx.x == 0) {
        unsigned int old = atomicAdd(&g_ticket, 1u);
        is_last = (old == (unsigned)gridDim.x - 1u);
    }
    __syncthreads();

    if (is_last) {
        float s = 0.0f;
        for (int i = threadIdx.x; i < (int)gridDim.x; i += NTHREADS)
            s += g_partials[i];
        #pragma unroll
        for (int m = 16; m > 0; m >>= 1)
            s += __shfl_xor_sync(0xFFFFFFFFu, s, m);
        if (lid == 0) warp_sums[wid] = s;
        __syncthreads();
        if (wid == 0) {
            float b = (lid < NTHREADS / 32) ? warp_sums[lid] : 0.0f;
            #pragma unroll
            for (int m = 4; m > 0; m >>= 1)
                b += __shfl_xor_sync(0xFFFFFFFFu, b, m);
            if (lid == 0) {
                out[0]   = b * inv_scale;   // LAMBDA1 = 1.0
                g_ticket = 0;               // reset for next graph replay
            }
        }
    }
}

extern "C" void kernel_launch(void* const* d_in, const int* in_sizes, int n_in,
                              void* d_out, int out_size) {
    const float4* y4  = (const float4*)d_in[0];
    long long n_elems = (long long)in_sizes[0];   // N * D
    long long nvec    = n_elems / 4;
    float inv_scale   = (float)(1.0 / (double)n_elems);

    loss_kernel<<<NBLOCKS, NTHREADS>>>(y4, nvec, (float*)d_out, inv_scale);
}